// round 5
// baseline (speedup 1.0000x reference)
#include <cuda_runtime.h>
#include <cuda_bf16.h>
#include <cstdint>

#define B_SZ 8
#define SEQ_L 2048
#define DM 256
#define DI 512
#define DS 16
#define DTR 16
#define DC 4
#define NL 3
#define BL (B_SZ * SEQ_L)   // 16384

#define SW128(o) ((o) ^ ((((o) >> 3)) & 0x70))

// ---------------- scratch (device globals) ----------------
__device__ __align__(1024) __nv_bfloat16 g_hn_b[(size_t)BL * DM];
__device__ __align__(1024) float         g_xz  [(size_t)BL * 2 * DI];
__device__ __align__(1024) __nv_bfloat16 g_u_b [(size_t)BL * DI];
__device__ __align__(1024) float         g_dbc [(size_t)BL * 48];
__device__ __align__(1024) float         g_dt  [(size_t)BL * DI];
__device__ __align__(1024) __nv_bfloat16 g_y_b [(size_t)BL * DI];
__device__ __align__(1024) __nv_bfloat16 g_win_b [(size_t)NL * 2 * DI * DM];
__device__ __align__(1024) __nv_bfloat16 g_wx_b  [(size_t)NL * 64 * DI];   // padded 48->64
__device__ __align__(1024) __nv_bfloat16 g_wout_b[(size_t)NL * DM * DI];

// ---------------- helpers ----------------
__device__ __forceinline__ uint32_t smem_u32(const void* p) {
    uint32_t a;
    asm("{ .reg .u64 t; cvta.to.shared.u64 t, %1; cvt.u32.u64 %0, t; }" : "=r"(a) : "l"(p));
    return a;
}
__device__ __forceinline__ void cp16(uint32_t dst, const void* src) {
    asm volatile("cp.async.cg.shared.global [%0], [%1], 16;" :: "r"(dst), "l"(src));
}
__device__ __forceinline__ void ldm_x4(uint32_t* r, uint32_t addr) {
    asm volatile("ldmatrix.sync.aligned.m8n8.x4.shared.b16 {%0,%1,%2,%3}, [%4];"
                 : "=r"(r[0]), "=r"(r[1]), "=r"(r[2]), "=r"(r[3]) : "r"(addr));
}
__device__ __forceinline__ void mma16816(float* d, const uint32_t* a, const uint32_t* b) {
    asm volatile("mma.sync.aligned.m16n8k16.row.col.f32.bf16.bf16.f32 "
                 "{%0,%1,%2,%3}, {%4,%5,%6,%7}, {%8,%9}, {%0,%1,%2,%3};"
                 : "+f"(d[0]), "+f"(d[1]), "+f"(d[2]), "+f"(d[3])
                 : "r"(a[0]), "r"(a[1]), "r"(a[2]), "r"(a[3]), "r"(b[0]), "r"(b[1]));
}

// ---------------- copy x -> out ----------------
__global__ void copy_f32(const float* __restrict__ in, float* __restrict__ out, int n) {
    int i = blockIdx.x * blockDim.x + threadIdx.x;
    if (i < n) out[i] = in[i];
}

// ---------------- weight conversion ----------------
__global__ void cvt_bf16_k(const float* __restrict__ s, __nv_bfloat16* __restrict__ d, int n) {
    int i = blockIdx.x * blockDim.x + threadIdx.x;
    if (i < n) d[i] = __float2bfloat16(s[i]);
}
__global__ void cvt_xproj_k(const float* __restrict__ s, __nv_bfloat16* __restrict__ d) {
    int i = blockIdx.x * blockDim.x + threadIdx.x;
    if (i >= NL * 64 * DI) return;
    int layer = i / (64 * DI);
    int rem   = i - layer * 64 * DI;
    int row   = rem / DI;
    int col   = rem - row * DI;
    float v = (row < 48) ? s[((size_t)layer * 48 + row) * DI + col] : 0.f;
    d[i] = __float2bfloat16(v);
}

// ---------------- layernorm -> bf16 ----------------
__global__ void layernorm_k(const float* __restrict__ h, const float* __restrict__ g,
                            const float* __restrict__ b, __nv_bfloat16* __restrict__ o) {
    __shared__ float red[16];
    __shared__ float smu, srv;
    int row = blockIdx.x;
    int tid = threadIdx.x;
    float v = h[(size_t)row * DM + tid];
    float s = v, s2 = v * v;
    #pragma unroll
    for (int off = 16; off; off >>= 1) {
        s  += __shfl_xor_sync(0xffffffffu, s,  off);
        s2 += __shfl_xor_sync(0xffffffffu, s2, off);
    }
    int w = tid >> 5;
    if ((tid & 31) == 0) { red[w] = s; red[8 + w] = s2; }
    __syncthreads();
    if (tid == 0) {
        float S = 0.f, S2 = 0.f;
        #pragma unroll
        for (int i = 0; i < 8; i++) { S += red[i]; S2 += red[8 + i]; }
        float mu = S * (1.f / DM);
        smu = mu;
        srv = rsqrtf(S2 * (1.f / DM) - mu * mu + 1e-5f);
    }
    __syncthreads();
    o[(size_t)row * DM + tid] = __float2bfloat16((v - smu) * srv * g[tid] + b[tid]);
}

// ---------------- bf16 tensor-core GEMM via mma.sync, 3-stage pipeline -------
// C[M,N] = A[M,K] @ W[N,K]^T.  Tiles 128 x BN x 64.
// EPI 0: store; EPI 1: store if n < nvalid; EPI 2: accumulate.
template <int BN, int EPI>
__global__ __launch_bounds__(256)
void mma_gemm(const __nv_bfloat16* __restrict__ A, const __nv_bfloat16* __restrict__ W,
              float* __restrict__ C, int K, int ldc, int nvalid) {
    constexpr int NF = BN / 16;
    constexpr int ABYTES = 128 * 128;
    constexpr int BBYTES = BN * 128;
    constexpr int BUF = ABYTES + BBYTES;

    extern __shared__ __align__(1024) char smem[];
    const uint32_t sbase = smem_u32(smem);

    const int tid = threadIdx.x;
    const int wid = tid >> 5, lane = tid & 31;
    const int wm = (wid & 3) * 32;
    const int wn = (wid >> 2) * (BN / 2);
    const int m0 = blockIdx.x * 128;
    const int n0 = blockIdx.y * BN;

    float acc[2][NF][4];
    #pragma unroll
    for (int i = 0; i < 2; i++)
        #pragma unroll
        for (int j = 0; j < NF; j++)
            #pragma unroll
            for (int q = 0; q < 4; q++) acc[i][j][q] = 0.f;

    const int nk = K >> 6;

    const int la_r = tid >> 3, la_c = (tid & 7) * 16;
    const int lb_r = tid >> 3, lb_c = (tid & 7) * 16;

    // per-thread ldmatrix offsets (stage-relative, swizzled once).
    // Correct SW128 mask for o = row*128 + c (c<128) is ((row & 7) * 16).
    uint32_t a_off[2];
    #pragma unroll
    for (int mt = 0; mt < 2; mt++) {
        int row = wm + mt * 16 + (lane & 15);
        a_off[mt] = row * 128 + (((lane >> 4) * 16) ^ ((row & 7) * 16));
    }
    uint32_t b_off[NF / 2];
    #pragma unroll
    for (int nf2 = 0; nf2 < NF / 2; nf2++) {
        int nrow = wn + nf2 * 16 + (lane & 7) + ((lane >> 4) << 3);
        b_off[nf2] = nrow * 128 + (((((lane >> 3) & 1)) * 16) ^ ((nrow & 7) * 16));
    }

    auto load_stage = [&](int stg, int chunk) {
        const uint32_t sb = sbase + stg * BUF;
        const int kc = chunk << 6;
        #pragma unroll
        for (int i = 0; i < 4; i++) {
            int r = la_r + i * 32;
            cp16(sb + SW128(r * 128 + la_c), A + (size_t)(m0 + r) * K + kc + la_c / 2);
        }
        #pragma unroll
        for (int i = 0; i < BN / 32; i++) {
            int r = lb_r + i * 32;
            cp16(sb + ABYTES + SW128(r * 128 + lb_c), W + (size_t)(n0 + r) * K + kc + lb_c / 2);
        }
    };

    load_stage(0, 0);
    asm volatile("cp.async.commit_group;");
    if (nk > 1) load_stage(1, 1);
    asm volatile("cp.async.commit_group;");

    int st = 0;
    for (int ic = 0; ic < nk; ic++) {
        asm volatile("cp.async.wait_group 1;");
        __syncthreads();
        if (ic + 2 < nk) {
            int ps = st + 2; if (ps >= 3) ps -= 3;
            load_stage(ps, ic + 2);
        }
        asm volatile("cp.async.commit_group;");

        const uint32_t abase = sbase + st * BUF;
        const uint32_t bbase = abase + ABYTES;
        #pragma unroll
        for (int ks = 0; ks < 4; ks++) {
            const uint32_t kx = ks * 32;   // bits 5-6; disjoint from hk bit 4; XOR-assoc with mask
            uint32_t afr[2][4];
            #pragma unroll
            for (int mt = 0; mt < 2; mt++)
                ldm_x4(afr[mt], abase + (a_off[mt] ^ kx));
            #pragma unroll
            for (int nf2 = 0; nf2 < NF / 2; nf2++) {
                uint32_t bfr[4];
                ldm_x4(bfr, bbase + (b_off[nf2] ^ kx));
                #pragma unroll
                for (int mt = 0; mt < 2; mt++) {
                    mma16816(acc[mt][2 * nf2],     afr[mt], bfr);
                    mma16816(acc[mt][2 * nf2 + 1], afr[mt], bfr + 2);
                }
            }
        }
        st++; if (st >= 3) st = 0;
    }

    // ---- epilogue ----
    #pragma unroll
    for (int mt = 0; mt < 2; mt++) {
        int r0 = m0 + wm + mt * 16 + (lane >> 2);
        #pragma unroll
        for (int nf = 0; nf < NF; nf++) {
            int cl = n0 + wn + nf * 8 + (lane & 3) * 2;
            float* p0 = C + (size_t)r0 * ldc + cl;
            float* p1 = p0 + (size_t)8 * ldc;
            if (EPI == 1 && cl >= nvalid) continue;
            if (EPI == 2) {
                float2 t0 = *(float2*)p0;
                float2 t1 = *(float2*)p1;
                t0.x += acc[mt][nf][0]; t0.y += acc[mt][nf][1];
                t1.x += acc[mt][nf][2]; t1.y += acc[mt][nf][3];
                *(float2*)p0 = t0;
                *(float2*)p1 = t1;
            } else {
                *(float2*)p0 = make_float2(acc[mt][nf][0], acc[mt][nf][1]);
                *(float2*)p1 = make_float2(acc[mt][nf][2], acc[mt][nf][3]);
            }
        }
    }
}

// ---------------- fp32 SGEMM (dt projection, K=16) + softplus ----------------
__global__ __launch_bounds__(256)
void sgemm_dt(const float* __restrict__ A, int lda,
              const float* __restrict__ W,
              const float* __restrict__ bias,
              float* __restrict__ C, int ldc,
              int M, int N, int K) {
    const int BM = 64, BN = 64, BK = 16;
    __shared__ float As[BK][BM + 4];
    __shared__ float Bs[BK][BN + 4];
    int tid = threadIdx.x;
    int m0 = blockIdx.x * BM;
    int n0 = blockIdx.y * BN;
    int tx = tid & 15, ty = tid >> 4;
    float acc[4][4] = {};
    int l_r = tid >> 2;
    int l_k = (tid & 3) * 4;

    for (int k0 = 0; k0 < K; k0 += BK) {
        float4 av = *(const float4*)(A + (size_t)(m0 + l_r) * lda + k0 + l_k);
        As[l_k + 0][l_r] = av.x; As[l_k + 1][l_r] = av.y;
        As[l_k + 2][l_r] = av.z; As[l_k + 3][l_r] = av.w;
        float4 bv = *(const float4*)(W + (size_t)(n0 + l_r) * K + k0 + l_k);
        Bs[l_k + 0][l_r] = bv.x; Bs[l_k + 1][l_r] = bv.y;
        Bs[l_k + 2][l_r] = bv.z; Bs[l_k + 3][l_r] = bv.w;
        __syncthreads();
        #pragma unroll
        for (int k = 0; k < BK; ++k) {
            float4 ar = *(const float4*)&As[k][ty * 4];
            float4 br = *(const float4*)&Bs[k][tx * 4];
            float a[4] = {ar.x, ar.y, ar.z, ar.w};
            float b[4] = {br.x, br.y, br.z, br.w};
            #pragma unroll
            for (int i = 0; i < 4; i++)
                #pragma unroll
                for (int j = 0; j < 4; j++)
                    acc[i][j] += a[i] * b[j];
        }
        __syncthreads();
    }
    #pragma unroll
    for (int i = 0; i < 4; i++) {
        int m = m0 + ty * 4 + i;
        #pragma unroll
        for (int j = 0; j < 4; j++) {
            int n = n0 + tx * 4 + j;
            float v = acc[i][j] + bias[n];
            v = fmaxf(v, 0.f) + log1pf(__expf(-fabsf(v)));
            C[(size_t)m * ldc + n] = v;
        }
    }
}

// ---------------- causal depthwise conv1d + SiLU -> bf16 ----------------
__global__ void conv_silu_k(const float* __restrict__ xz, const float* __restrict__ w,
                            const float* __restrict__ bias,
                            __nv_bfloat16* __restrict__ ub) {
    int idx = blockIdx.x * blockDim.x + threadIdx.x;
    if (idx >= BL * DI) return;
    int d   = idx & (DI - 1);
    int row = idx >> 9;
    int t   = row & (SEQ_L - 1);
    float acc = bias[d];
    #pragma unroll
    for (int k = 0; k < DC; ++k) {
        int tt = t - (DC - 1) + k;
        if (tt >= 0) acc += w[d * DC + k] * xz[(size_t)(row - (DC - 1) + k) * (2 * DI) + d];
    }
    float v = acc / (1.f + __expf(-acc));
    ub[idx] = __float2bfloat16(v);
}

// ---------------- selective scan (fused gating) ----------------
#define TCH 64
__global__ __launch_bounds__(256)
void scan_k(const float* __restrict__ dt, const __nv_bfloat16* __restrict__ u,
            const float* __restrict__ dbc, const float* __restrict__ xz,
            const float* __restrict__ A_log, const float* __restrict__ Dp,
            __nv_bfloat16* __restrict__ y) {
    __shared__ float s_dt[TCH][16];
    __shared__ float s_u [TCH][16];
    __shared__ float s_b [TCH][16];
    __shared__ float s_c [TCH][16];
    __shared__ float s_z [TCH][16];

    int b  = blockIdx.x >> 5;
    int d0 = (blockIdx.x & 31) * 16;
    int c  = threadIdx.x >> 4;
    int s  = threadIdx.x & 15;
    int d  = d0 + c;

    float Acoef = -__expf(A_log[d * DS + s]);
    float Dv = Dp[d];
    float h = 0.f;

    size_t base = (size_t)b * SEQ_L;
    for (int t0 = 0; t0 < SEQ_L; t0 += TCH) {
        __syncthreads();
        for (int j = threadIdx.x; j < TCH * 16; j += 256) {
            int r = j >> 4, cc = j & 15;
            size_t row = base + t0 + r;
            s_dt[r][cc] = dt[row * DI + d0 + cc];
            s_u [r][cc] = __bfloat162float(u[row * DI + d0 + cc]);
            s_z [r][cc] = xz[row * (2 * DI) + DI + d0 + cc];
            s_b [r][cc] = dbc[row * 48 + 16 + cc];
            s_c [r][cc] = dbc[row * 48 + 32 + cc];
        }
        __syncthreads();
        #pragma unroll 4
        for (int tt = 0; tt < TCH; ++tt) {
            float dtv = s_dt[tt][c];
            float uv  = s_u[tt][c];
            float dA  = __expf(dtv * Acoef);
            h = h * dA + dtv * uv * s_b[tt][s];
            float yp = h * s_c[tt][s];
            yp += __shfl_xor_sync(0xffffffffu, yp, 8);
            yp += __shfl_xor_sync(0xffffffffu, yp, 4);
            yp += __shfl_xor_sync(0xffffffffu, yp, 2);
            yp += __shfl_xor_sync(0xffffffffu, yp, 1);
            if (s == 0) {
                float zv = s_z[tt][c];
                float sz = zv * __frcp_rn(1.f + __expf(-zv));
                y[(base + t0 + tt) * DI + d] = __float2bfloat16((yp + uv * Dv) * sz);
            }
        }
    }
}

// ---------------- host launcher ----------------
extern "C" void kernel_launch(void* const* d_in, const int* in_sizes, int n_in,
                              void* d_out, int out_size) {
    const float* x        = (const float*)d_in[0];
    const float* ln_g     = (const float*)d_in[1];
    const float* ln_b     = (const float*)d_in[2];
    const float* in_w     = (const float*)d_in[3];
    const float* conv_w   = (const float*)d_in[4];
    const float* conv_b   = (const float*)d_in[5];
    const float* xproj_w  = (const float*)d_in[6];
    const float* dtproj_w = (const float*)d_in[7];
    const float* dtproj_b = (const float*)d_in[8];
    const float* A_log    = (const float*)d_in[9];
    const float* Dp       = (const float*)d_in[10];
    const float* out_w    = (const float*)d_in[11];
    float* out = (float*)d_out;

    __nv_bfloat16 *hn_b, *u_b, *y_b, *win_b, *wx_b, *wout_b;
    float *xz, *dbc, *dt;
    cudaGetSymbolAddress((void**)&hn_b,  g_hn_b);
    cudaGetSymbolAddress((void**)&xz,    g_xz);
    cudaGetSymbolAddress((void**)&u_b,   g_u_b);
    cudaGetSymbolAddress((void**)&dbc,   g_dbc);
    cudaGetSymbolAddress((void**)&dt,    g_dt);
    cudaGetSymbolAddress((void**)&y_b,   g_y_b);
    cudaGetSymbolAddress((void**)&win_b, g_win_b);
    cudaGetSymbolAddress((void**)&wx_b,  g_wx_b);
    cudaGetSymbolAddress((void**)&wout_b,g_wout_b);

    const int SM128 = 3 * (128 + 128) * 128;   // 98304
    const int SM64  = 3 * (128 + 64) * 128;    // 73728
    cudaFuncSetAttribute(mma_gemm<128, 0>, cudaFuncAttributeMaxDynamicSharedMemorySize, SM128);
    cudaFuncSetAttribute(mma_gemm<64, 1>,  cudaFuncAttributeMaxDynamicSharedMemorySize, SM64);
    cudaFuncSetAttribute(mma_gemm<128, 2>, cudaFuncAttributeMaxDynamicSharedMemorySize, SM128);

    {
        int n1 = NL * 2 * DI * DM;
        cvt_bf16_k<<<(n1 + 255) / 256, 256>>>(in_w, win_b, n1);
        int n2 = NL * DM * DI;
        cvt_bf16_k<<<(n2 + 255) / 256, 256>>>(out_w, wout_b, n2);
        int n3 = NL * 64 * DI;
        cvt_xproj_k<<<(n3 + 255) / 256, 256>>>(xproj_w, wx_b);
    }

    const int n_out = BL * DM;
    copy_f32<<<(n_out + 255) / 256, 256>>>(x, out, n_out);

    for (int i = 0; i < NL; ++i) {
        layernorm_k<<<BL, 256>>>(out, ln_g, ln_b, hn_b);
        mma_gemm<128, 0><<<dim3(BL / 128, 8), 256, SM128>>>(
            hn_b, win_b + (size_t)i * 2 * DI * DM, xz, DM, 2 * DI, 2 * DI);
        conv_silu_k<<<(BL * DI + 255) / 256, 256>>>(
            xz, conv_w + (size_t)i * DI * DC, conv_b + (size_t)i * DI, u_b);
        mma_gemm<64, 1><<<dim3(BL / 128, 1), 256, SM64>>>(
            u_b, wx_b + (size_t)i * 64 * DI, dbc, DI, 48, 48);
        sgemm_dt<<<dim3(BL / 64, DI / 64), 256>>>(
            dbc, 48, dtproj_w + (size_t)i * DI * DTR, dtproj_b + (size_t)i * DI,
            dt, DI, BL, DI, DTR);
        scan_k<<<B_SZ * 32, 256>>>(dt, u_b, dbc, xz,
                                   A_log + (size_t)i * DI * DS, Dp + (size_t)i * DI, y_b);
        mma_gemm<128, 2><<<dim3(BL / 128, 2), 256, SM128>>>(
            y_b, wout_b + (size_t)i * DM * DI, out, DI, DM, DM);
    }
}